// round 5
// baseline (speedup 1.0000x reference)
#include <cuda_runtime.h>
#include <math.h>
#include <stdint.h>

#define BATCH 2
#define SEQ   4096
#define CHN   1280
#define HEADS 8
#define HDIM  160
#define BHN   16          // BATCH*HEADS
#define MTOT  8192        // BATCH*SEQ

#define QT 64
#define KTL 64
#define KSTR 68
#define SSTR 68

// Scratch (allocation-free rule: __device__ globals)
__device__ float g_q [(size_t)BHN * SEQ * HDIM];   // [bh][s][d]
__device__ float g_kT[(size_t)BHN * HDIM * SEQ];   // [bh][d][s]  (transposed)
__device__ float g_vT[(size_t)BHN * HDIM * SEQ];   // [bh][d][s]  (transposed)
__device__ float g_ao[(size_t)MTOT * CHN];         // [b*s][h*d]

// ---------------------------------------------------------------------------
// Kernel 1: fused QKV projection.  X[8192,1280] @ W[1280,1280] (z selects W).
// z=0 -> Q row-major per head; z=1,2 -> K,V transposed per head.
// ---------------------------------------------------------------------------
__global__ __launch_bounds__(256) void qkv_gemm(
    const float* __restrict__ X, const float* __restrict__ Wq,
    const float* __restrict__ Wk, const float* __restrict__ Wv)
{
    __shared__ float As[16][132];
    __shared__ float Bs[16][132];

    const int tid = threadIdx.x;
    const int tx = tid & 15, ty = tid >> 4;
    const int row0 = blockIdx.y * 128;
    const int col0 = blockIdx.x * 128;
    const float* __restrict__ W =
        (blockIdx.z == 0) ? Wq : (blockIdx.z == 1 ? Wk : Wv);

    float acc[8][8];
#pragma unroll
    for (int i = 0; i < 8; i++)
#pragma unroll
        for (int j = 0; j < 8; j++) acc[i][j] = 0.f;

    const int arow = tid >> 2;
    const int acol = (tid & 3) << 2;
    const int brow = tid >> 5;
    const int bcol = (tid & 31) << 2;

    for (int kb = 0; kb < CHN; kb += 16) {
        float4 a0 = *(const float4*)&X[(size_t)(row0 + arow) * CHN + kb + acol];
        float4 a1 = *(const float4*)&X[(size_t)(row0 + arow + 64) * CHN + kb + acol];
        As[acol + 0][arow] = a0.x; As[acol + 1][arow] = a0.y;
        As[acol + 2][arow] = a0.z; As[acol + 3][arow] = a0.w;
        As[acol + 0][arow + 64] = a1.x; As[acol + 1][arow + 64] = a1.y;
        As[acol + 2][arow + 64] = a1.z; As[acol + 3][arow + 64] = a1.w;
        *(float4*)&Bs[brow][bcol] =
            *(const float4*)&W[(size_t)(kb + brow) * CHN + col0 + bcol];
        *(float4*)&Bs[brow + 8][bcol] =
            *(const float4*)&W[(size_t)(kb + brow + 8) * CHN + col0 + bcol];
        __syncthreads();
#pragma unroll
        for (int k = 0; k < 16; k++) {
            float a[8], b[8];
            *(float4*)&a[0] = *(float4*)&As[k][ty * 8];
            *(float4*)&a[4] = *(float4*)&As[k][ty * 8 + 4];
            *(float4*)&b[0] = *(float4*)&Bs[k][tx * 8];
            *(float4*)&b[4] = *(float4*)&Bs[k][tx * 8 + 4];
#pragma unroll
            for (int i = 0; i < 8; i++)
#pragma unroll
                for (int j = 0; j < 8; j++)
                    acc[i][j] += a[i] * b[j];
        }
        __syncthreads();
    }

    const int m0 = row0 + ty * 8;
    const int n0 = col0 + tx * 8;
    if (blockIdx.z == 0) {
#pragma unroll
        for (int i = 0; i < 8; i++) {
            int m = m0 + i, b = m >> 12, s = m & (SEQ - 1);
#pragma unroll
            for (int j4 = 0; j4 < 8; j4 += 4) {
                int n = n0 + j4, h = n / HDIM, d = n - h * HDIM;
                float4 v = make_float4(acc[i][j4], acc[i][j4 + 1],
                                       acc[i][j4 + 2], acc[i][j4 + 3]);
                *(float4*)&g_q[((size_t)(b * HEADS + h) * SEQ + s) * HDIM + d] = v;
            }
        }
    } else {
        float* __restrict__ G = (blockIdx.z == 1) ? g_kT : g_vT;
#pragma unroll
        for (int j = 0; j < 8; j++) {
            int n = n0 + j, h = n / HDIM, d = n - h * HDIM;
#pragma unroll
            for (int i4 = 0; i4 < 8; i4 += 4) {
                int m = m0 + i4, b = m >> 12, s = m & (SEQ - 1);
                float4 v = make_float4(acc[i4][j], acc[i4 + 1][j],
                                       acc[i4 + 2][j], acc[i4 + 3][j]);
                *(float4*)&G[((size_t)(b * HEADS + h) * HDIM + d) * SEQ + s] = v;
            }
        }
    }
}

// ---------------------------------------------------------------------------
// Kernel 2: flash attention, 64-query x 64-key tiles, online softmax.
// Thread map: (tx,ty) 16x16; S-tile rows = ty*4..+3, cols = tx*4..+3.
// O accumulator: 4 rows x 10 cols (cols c = tx + 16*u).
// ---------------------------------------------------------------------------
__global__ __launch_bounds__(256) void attn_kernel()
{
    extern __shared__ float smem[];
    float* sQ  = smem;                     // QT*HDIM         (10240)
    float* sKT = sQ  + QT * HDIM;          // HDIM*KSTR       (10880)
    float* sVT = sKT + HDIM * KSTR;        // HDIM*KSTR       (10880)
    float* sS  = sVT + HDIM * KSTR;        // QT*SSTR         (4352)

    const int bh = blockIdx.y;
    const int q0 = blockIdx.x * QT;
    const int tid = threadIdx.x;
    const int tx = tid & 15, ty = tid >> 4;

    const float scale = 0.07905694150420949f;  // 1/sqrt(160)

    const float* __restrict__ Qg = g_q + ((size_t)bh * SEQ + q0) * HDIM;
    for (int i = tid * 4; i < QT * HDIM; i += 1024) {
        float4 v = *(const float4*)&Qg[i];
        v.x *= scale; v.y *= scale; v.z *= scale; v.w *= scale;
        *(float4*)&sQ[i] = v;
    }

    float acc[4][10];
#pragma unroll
    for (int r = 0; r < 4; r++)
#pragma unroll
        for (int u = 0; u < 10; u++) acc[r][u] = 0.f;
    float mrow[4], lrow[4];
#pragma unroll
    for (int r = 0; r < 4; r++) { mrow[r] = -INFINITY; lrow[r] = 0.f; }

    const float* __restrict__ Kg = g_kT + (size_t)bh * HDIM * SEQ;
    const float* __restrict__ Vg = g_vT + (size_t)bh * HDIM * SEQ;

    for (int kt = 0; kt < SEQ; kt += KTL) {
        __syncthreads();   // prev PV done before K/V overwrite
        for (int i = tid; i < HDIM * (KTL / 4); i += 256) {
            int d  = i >> 4;
            int j4 = (i & 15) << 2;
            *(float4*)&sKT[d * KSTR + j4] =
                *(const float4*)&Kg[(size_t)d * SEQ + kt + j4];
            *(float4*)&sVT[d * KSTR + j4] =
                *(const float4*)&Vg[(size_t)d * SEQ + kt + j4];
        }
        __syncthreads();

        // ---- S = (Q*scale) @ K^T  (64x64 tile) ----
        float s[4][4];
#pragma unroll
        for (int r = 0; r < 4; r++)
#pragma unroll
            for (int c = 0; c < 4; c++) s[r][c] = 0.f;

#pragma unroll 4
        for (int k = 0; k < HDIM; k += 4) {
            float qf[4][4];
#pragma unroll
            for (int rr = 0; rr < 4; rr++)
                *(float4*)qf[rr] = *(const float4*)&sQ[(ty * 4 + rr) * HDIM + k];
#pragma unroll
            for (int i = 0; i < 4; i++) {
                float4 kv = *(const float4*)&sKT[(k + i) * KSTR + tx * 4];
#pragma unroll
                for (int rr = 0; rr < 4; rr++) {
                    s[rr][0] += qf[rr][i] * kv.x;
                    s[rr][1] += qf[rr][i] * kv.y;
                    s[rr][2] += qf[rr][i] * kv.z;
                    s[rr][3] += qf[rr][i] * kv.w;
                }
            }
        }

        // ---- online softmax (row stats reduced over the 16 tx threads) ----
#pragma unroll
        for (int rr = 0; rr < 4; rr++) {
            float mx = fmaxf(fmaxf(s[rr][0], s[rr][1]), fmaxf(s[rr][2], s[rr][3]));
#pragma unroll
            for (int o = 8; o > 0; o >>= 1)
                mx = fmaxf(mx, __shfl_xor_sync(0xffffffffu, mx, o));
            float mnew  = fmaxf(mrow[rr], mx);
            float alpha = __expf(mrow[rr] - mnew);
            float p0 = __expf(s[rr][0] - mnew);
            float p1 = __expf(s[rr][1] - mnew);
            float p2 = __expf(s[rr][2] - mnew);
            float p3 = __expf(s[rr][3] - mnew);
            float rs = (p0 + p1) + (p2 + p3);
#pragma unroll
            for (int o = 8; o > 0; o >>= 1)
                rs += __shfl_xor_sync(0xffffffffu, rs, o);
            lrow[rr] = lrow[rr] * alpha + rs;
            mrow[rr] = mnew;
#pragma unroll
            for (int u = 0; u < 10; u++) acc[rr][u] *= alpha;
            *(float4*)&sS[(ty * 4 + rr) * SSTR + tx * 4] = make_float4(p0, p1, p2, p3);
        }
        __syncthreads();

        // ---- O += P @ V  (uses V^T tile; cols c = tx + 16u) ----
#pragma unroll 4
        for (int j = 0; j < KTL; j += 4) {
            float pf[4][4];
#pragma unroll
            for (int rr = 0; rr < 4; rr++)
                *(float4*)pf[rr] = *(const float4*)&sS[(ty * 4 + rr) * SSTR + j];
#pragma unroll
            for (int u = 0; u < 10; u++) {
                float4 vv = *(const float4*)&sVT[(tx + 16 * u) * KSTR + j];
#pragma unroll
                for (int rr = 0; rr < 4; rr++) {
                    acc[rr][u] += pf[rr][0] * vv.x + pf[rr][1] * vv.y +
                                  pf[rr][2] * vv.z + pf[rr][3] * vv.w;
                }
            }
        }
    }

    const int b = bh >> 3, h = bh & 7;
#pragma unroll
    for (int rr = 0; rr < 4; rr++) {
        float inv = 1.0f / lrow[rr];
        float* O = g_ao + (size_t)(b * SEQ + q0 + ty * 4 + rr) * CHN + h * HDIM + tx;
#pragma unroll
        for (int u = 0; u < 10; u++) O[16 * u] = acc[rr][u] * inv;
    }
}

// ---------------------------------------------------------------------------
// Kernel 3: output projection + bias.  g_ao[8192,1280] @ w_out + b_out.
// ---------------------------------------------------------------------------
__global__ __launch_bounds__(256) void out_gemm(
    const float* __restrict__ W, const float* __restrict__ bias,
    float* __restrict__ out)
{
    __shared__ float As[16][132];
    __shared__ float Bs[16][132];

    const int tid = threadIdx.x;
    const int tx = tid & 15, ty = tid >> 4;
    const int row0 = blockIdx.y * 128;
    const int col0 = blockIdx.x * 128;

    float acc[8][8];
#pragma unroll
    for (int i = 0; i < 8; i++)
#pragma unroll
        for (int j = 0; j < 8; j++) acc[i][j] = 0.f;

    const int arow = tid >> 2;
    const int acol = (tid & 3) << 2;
    const int brow = tid >> 5;
    const int bcol = (tid & 31) << 2;

    for (int kb = 0; kb < CHN; kb += 16) {
        float4 a0 = *(const float4*)&g_ao[(size_t)(row0 + arow) * CHN + kb + acol];
        float4 a1 = *(const float4*)&g_ao[(size_t)(row0 + arow + 64) * CHN + kb + acol];
        As[acol + 0][arow] = a0.x; As[acol + 1][arow] = a0.y;
        As[acol + 2][arow] = a0.z; As[acol + 3][arow] = a0.w;
        As[acol + 0][arow + 64] = a1.x; As[acol + 1][arow + 64] = a1.y;
        As[acol + 2][arow + 64] = a1.z; As[acol + 3][arow + 64] = a1.w;
        *(float4*)&Bs[brow][bcol] =
            *(const float4*)&W[(size_t)(kb + brow) * CHN + col0 + bcol];
        *(float4*)&Bs[brow + 8][bcol] =
            *(const float4*)&W[(size_t)(kb + brow + 8) * CHN + col0 + bcol];
        __syncthreads();
#pragma unroll
        for (int k = 0; k < 16; k++) {
            float a[8], b[8];
            *(float4*)&a[0] = *(float4*)&As[k][ty * 8];
            *(float4*)&a[4] = *(float4*)&As[k][ty * 8 + 4];
            *(float4*)&b[0] = *(float4*)&Bs[k][tx * 8];
            *(float4*)&b[4] = *(float4*)&Bs[k][tx * 8 + 4];
#pragma unroll
            for (int i = 0; i < 8; i++)
#pragma unroll
                for (int j = 0; j < 8; j++)
                    acc[i][j] += a[i] * b[j];
        }
        __syncthreads();
    }

    const int m0 = row0 + ty * 8;
    const int n0 = col0 + tx * 8;
#pragma unroll
    for (int i = 0; i < 8; i++) {
#pragma unroll
        for (int j4 = 0; j4 < 8; j4 += 4) {
            int n = n0 + j4;
            float4 bv = *(const float4*)&bias[n];
            float4 v = make_float4(acc[i][j4] + bv.x, acc[i][j4 + 1] + bv.y,
                                   acc[i][j4 + 2] + bv.z, acc[i][j4 + 3] + bv.w);
            *(float4*)&out[(size_t)(m0 + i) * CHN + n] = v;
        }
    }
}

// ---------------------------------------------------------------------------
extern "C" void kernel_launch(void* const* d_in, const int* in_sizes, int n_in,
                              void* d_out, int out_size)
{
    const float* X    = (const float*)d_in[0];
    const float* Wq   = (const float*)d_in[1];
    const float* Wk   = (const float*)d_in[2];
    const float* Wv   = (const float*)d_in[3];
    const float* Wout = (const float*)d_in[4];
    const float* bout = (const float*)d_in[5];
    float* out = (float*)d_out;

    qkv_gemm<<<dim3(CHN / 128, MTOT / 128, 3), 256>>>(X, Wq, Wk, Wv);

    const int smem_bytes =
        (QT * HDIM + 2 * HDIM * KSTR + QT * SSTR) * (int)sizeof(float);  // 145408
    cudaFuncSetAttribute(attn_kernel,
                         cudaFuncAttributeMaxDynamicSharedMemorySize, smem_bytes);
    attn_kernel<<<dim3(SEQ / QT, BHN), 256, smem_bytes>>>();

    out_gemm<<<dim3(CHN / 128, MTOT / 128), 256>>>(Wout, bout, out);
}

// round 6
// speedup vs baseline: 2.3504x; 2.3504x over previous
#include <cuda_runtime.h>
#include <math.h>
#include <stdint.h>

#define BATCH 2
#define SEQ   4096
#define CHN   1280
#define HEADS 8
#define HDIM  160
#define BHN   16          // BATCH*HEADS
#define MTOT  8192        // BATCH*SEQ

// Scratch (allocation-free rule: __device__ globals)
__device__ float g_q [(size_t)BHN * SEQ * HDIM];   // [bh][s][d]
__device__ float g_kT[(size_t)BHN * HDIM * SEQ];   // [bh][d][s]
__device__ float g_vT[(size_t)BHN * HDIM * SEQ];   // [bh][d][s]
__device__ float g_ao[(size_t)MTOT * CHN];         // [b*s][h*d]

// ---------------------------------------------------------------------------
// helpers
// ---------------------------------------------------------------------------
__device__ __forceinline__ unsigned f2tf(float x) {
    unsigned r;
    asm("cvt.rna.tf32.f32 %0, %1;" : "=r"(r) : "f"(x));
    return r;
}
__device__ __forceinline__ float uaf(unsigned u) { return __uint_as_float(u); }

// D = A(16x8) * B(8x8) + D, tf32 inputs, f32 accum
__device__ __forceinline__ void mma8(float* c, const unsigned* a, const unsigned* b) {
    asm volatile(
        "mma.sync.aligned.m16n8k8.row.col.f32.tf32.tf32.f32 "
        "{%0,%1,%2,%3}, {%4,%5,%6,%7}, {%8,%9}, {%0,%1,%2,%3};\n"
        : "+f"(c[0]), "+f"(c[1]), "+f"(c[2]), "+f"(c[3])
        : "r"(a[0]), "r"(a[1]), "r"(a[2]), "r"(a[3]), "r"(b[0]), "r"(b[1]));
}

// exp(x) for x <= 0 on the FMA pipe (no MUFU). |rel err| ~ 2.4e-6.
__device__ __forceinline__ float fast_exp(float x) {
    x = fmaxf(x, -80.0f);
    float y = x * 1.4426950408889634f;
    float t = y + 12582912.0f;                 // round-to-nearest-int in mantissa
    int   e = __float_as_int(t);               // low bits hold n (bias bits shift out)
    float n = t - 12582912.0f;
    float f = y - n;                           // [-0.5, 0.5]
    float p = 1.3333558e-3f;
    p = fmaf(p, f, 9.6181291e-3f);
    p = fmaf(p, f, 5.5504109e-2f);
    p = fmaf(p, f, 2.4022651e-1f);
    p = fmaf(p, f, 6.9314718e-1f);
    p = fmaf(p, f, 1.0f);
    return __int_as_float(__float_as_int(p) + (e << 23));
}

// ---------------------------------------------------------------------------
// shared GEMM core: C[128x128] frags from A[*,1280] @ B[1280,*] (tf32 mma)
// warp layout 2(m) x 4(n); warp tile 64x32 -> c[16][4] (mt*4+nt)
// ---------------------------------------------------------------------------
#define ASTR 36
#define BSTR 136

__device__ __forceinline__ void gemm_frags(
    const float* __restrict__ A, const float* __restrict__ B,
    int row0, int col0, float c[16][4], float* As, float* Bs)
{
    const int tid = threadIdx.x;
    const int warp = tid >> 5, lane = tid & 31;
    const int g = lane >> 2, t = lane & 3;
    const int wm = warp >> 2, wn = warp & 3;

    const int ar = tid >> 3, akc = (tid & 7) << 2;
    const int br = tid >> 5, bcc = (tid & 31) << 2;

    for (int kb = 0; kb < CHN; kb += 32) {
#pragma unroll
        for (int it = 0; it < 4; it++) {
            float4 v = *(const float4*)&A[(size_t)(row0 + ar + it * 32) * CHN + kb + akc];
            float4 w = make_float4(uaf(f2tf(v.x)), uaf(f2tf(v.y)),
                                   uaf(f2tf(v.z)), uaf(f2tf(v.w)));
            *(float4*)&As[(ar + it * 32) * ASTR + akc] = w;
        }
#pragma unroll
        for (int it = 0; it < 4; it++) {
            float4 v = *(const float4*)&B[(size_t)(kb + br + it * 8) * CHN + col0 + bcc];
            float4 w = make_float4(uaf(f2tf(v.x)), uaf(f2tf(v.y)),
                                   uaf(f2tf(v.z)), uaf(f2tf(v.w)));
            *(float4*)&Bs[(br + it * 8) * BSTR + bcc] = w;
        }
        __syncthreads();
#pragma unroll
        for (int ks = 0; ks < 4; ks++) {
            unsigned af[4][4], bf[4][2];
#pragma unroll
            for (int mt = 0; mt < 4; mt++) {
                int r = wm * 64 + mt * 16 + g;
                af[mt][0] = __float_as_uint(As[r * ASTR + ks * 8 + t]);
                af[mt][1] = __float_as_uint(As[(r + 8) * ASTR + ks * 8 + t]);
                af[mt][2] = __float_as_uint(As[r * ASTR + ks * 8 + t + 4]);
                af[mt][3] = __float_as_uint(As[(r + 8) * ASTR + ks * 8 + t + 4]);
            }
#pragma unroll
            for (int nt = 0; nt < 4; nt++) {
                int cc = wn * 32 + nt * 8 + g;
                bf[nt][0] = __float_as_uint(Bs[(ks * 8 + t) * BSTR + cc]);
                bf[nt][1] = __float_as_uint(Bs[(ks * 8 + t + 4) * BSTR + cc]);
            }
#pragma unroll
            for (int mt = 0; mt < 4; mt++)
#pragma unroll
                for (int nt = 0; nt < 4; nt++)
                    mma8(c[mt * 4 + nt], af[mt], bf[nt]);
        }
        __syncthreads();
    }
}

// ---------------------------------------------------------------------------
// Kernel 1: fused QKV projection (tf32 mma). z selects W and destination.
// ---------------------------------------------------------------------------
__global__ __launch_bounds__(256) void qkv_gemm(
    const float* __restrict__ X, const float* __restrict__ Wq,
    const float* __restrict__ Wk, const float* __restrict__ Wv)
{
    __shared__ float As[128 * ASTR];
    __shared__ float Bs[32 * BSTR];

    const float* __restrict__ W =
        (blockIdx.z == 0) ? Wq : (blockIdx.z == 1 ? Wk : Wv);

    float c[16][4];
#pragma unroll
    for (int i = 0; i < 16; i++)
#pragma unroll
        for (int j = 0; j < 4; j++) c[i][j] = 0.f;

    gemm_frags(X, W, blockIdx.y * 128, blockIdx.x * 128, c, As, Bs);

    const int lane = threadIdx.x & 31, warp = threadIdx.x >> 5;
    const int g = lane >> 2, t = lane & 3;
    const int wm = warp >> 2, wn = warp & 3;

#pragma unroll
    for (int mt = 0; mt < 4; mt++) {
#pragma unroll
        for (int nt = 0; nt < 4; nt++) {
            int rowb = blockIdx.y * 128 + wm * 64 + mt * 16 + g;
            int col  = blockIdx.x * 128 + wn * 32 + nt * 8 + 2 * t;
            if (blockIdx.z == 0) {
#pragma unroll
                for (int half = 0; half < 2; half++) {
                    int row = rowb + half * 8;
                    int b = row >> 12, s = row & (SEQ - 1);
                    int h = col / HDIM, d = col - h * HDIM;
                    float2 v = make_float2(c[mt * 4 + nt][half * 2],
                                           c[mt * 4 + nt][half * 2 + 1]);
                    *(float2*)&g_q[((size_t)(b * HEADS + h) * SEQ + s) * HDIM + d] = v;
                }
            } else {
                float* __restrict__ G = (blockIdx.z == 1) ? g_kT : g_vT;
#pragma unroll
                for (int i = 0; i < 4; i++) {
                    int row = rowb + (i >> 1) * 8;
                    int cj  = col + (i & 1);
                    int b = row >> 12, s = row & (SEQ - 1);
                    int h = cj / HDIM, d = cj - h * HDIM;
                    G[((size_t)(b * HEADS + h) * HDIM + d) * SEQ + s] = c[mt * 4 + nt][i];
                }
            }
        }
    }
}

// ---------------------------------------------------------------------------
// Kernel 2: flash attention via tf32 mma. 64q x 64k tiles, online softmax.
// Warp layout: 4(m) x 2(n). S: warp 16x32. PV: warp 16x80.
// ---------------------------------------------------------------------------
#define QSTR 164
#define KSTR 72
#define VSTR 68
#define PSTR 68

__global__ __launch_bounds__(256) void attn_kernel()
{
    extern __shared__ float smem[];
    float* sQ  = smem;                 // 64*164  = 10496
    float* sK  = sQ + 64 * QSTR;       // 160*72  = 11520  [d][key]
    float* sV  = sK + HDIM * KSTR;     // 160*68  = 10880  [d][key]
    float* sP  = sV + HDIM * VSTR;     // 64*68   = 4352
    float* sMx = sP + 64 * PSTR;       // 128
    float* sSm = sMx + 128;            // 128

    const int bh = blockIdx.y;
    const int q0 = blockIdx.x * 64;
    const int tid = threadIdx.x, warp = tid >> 5, lane = tid & 31;
    const int g = lane >> 2, t = lane & 3;
    const int wm = warp >> 1, wn = warp & 1;
    const int r0 = wm * 16 + g, r1 = r0 + 8;

    const float scale = 0.07905694150420949f;  // 1/sqrt(160)

    const float* __restrict__ Qg = g_q + ((size_t)bh * SEQ + q0) * HDIM;
    for (int i = tid * 4; i < 64 * HDIM; i += 1024) {
        int r = i / HDIM, cc = i - r * HDIM;
        float4 v = *(const float4*)&Qg[(size_t)r * HDIM + cc];
        float4 w = make_float4(uaf(f2tf(v.x * scale)), uaf(f2tf(v.y * scale)),
                               uaf(f2tf(v.z * scale)), uaf(f2tf(v.w * scale)));
        *(float4*)&sQ[r * QSTR + cc] = w;
    }

    float o[10][4];
#pragma unroll
    for (int u = 0; u < 10; u++)
#pragma unroll
        for (int j = 0; j < 4; j++) o[u][j] = 0.f;
    float m0v = -1e30f, m1v = -1e30f, l0 = 0.f, l1 = 0.f;

    const float* __restrict__ Kg = g_kT + (size_t)bh * HDIM * SEQ;
    const float* __restrict__ Vg = g_vT + (size_t)bh * HDIM * SEQ;

    for (int kt = 0; kt < SEQ; kt += 64) {
        __syncthreads();   // prev PV done (first iter: orders sQ fill too)
        for (int i = tid; i < HDIM * 16; i += 256) {
            int d = i >> 4, j4 = (i & 15) << 2;
            float4 kv = *(const float4*)&Kg[(size_t)d * SEQ + kt + j4];
            float4 vv = *(const float4*)&Vg[(size_t)d * SEQ + kt + j4];
            float4 kw = make_float4(uaf(f2tf(kv.x)), uaf(f2tf(kv.y)),
                                    uaf(f2tf(kv.z)), uaf(f2tf(kv.w)));
            float4 vw = make_float4(uaf(f2tf(vv.x)), uaf(f2tf(vv.y)),
                                    uaf(f2tf(vv.z)), uaf(f2tf(vv.w)));
            *(float4*)&sK[d * KSTR + j4] = kw;
            *(float4*)&sV[d * VSTR + j4] = vw;
        }
        __syncthreads();

        // ---- S = Q @ K^T (scaled Q) ----
        float s[4][4];
#pragma unroll
        for (int nt = 0; nt < 4; nt++)
#pragma unroll
            for (int j = 0; j < 4; j++) s[nt][j] = 0.f;

#pragma unroll
        for (int ks = 0; ks < 20; ks++) {
            unsigned af[4];
            af[0] = __float_as_uint(sQ[r0 * QSTR + ks * 8 + t]);
            af[1] = __float_as_uint(sQ[r1 * QSTR + ks * 8 + t]);
            af[2] = __float_as_uint(sQ[r0 * QSTR + ks * 8 + t + 4]);
            af[3] = __float_as_uint(sQ[r1 * QSTR + ks * 8 + t + 4]);
#pragma unroll
            for (int nt = 0; nt < 4; nt++) {
                int cc = wn * 32 + nt * 8 + g;
                unsigned bf[2];
                bf[0] = __float_as_uint(sK[(ks * 8 + t) * KSTR + cc]);
                bf[1] = __float_as_uint(sK[(ks * 8 + t + 4) * KSTR + cc]);
                mma8(s[nt], af, bf);
            }
        }

        // ---- online softmax ----
        float mx0 = fmaxf(fmaxf(s[0][0], s[0][1]), fmaxf(s[1][0], s[1][1]));
        mx0 = fmaxf(mx0, fmaxf(fmaxf(s[2][0], s[2][1]), fmaxf(s[3][0], s[3][1])));
        float mx1 = fmaxf(fmaxf(s[0][2], s[0][3]), fmaxf(s[1][2], s[1][3]));
        mx1 = fmaxf(mx1, fmaxf(fmaxf(s[2][2], s[2][3]), fmaxf(s[3][2], s[3][3])));
        mx0 = fmaxf(mx0, __shfl_xor_sync(0xffffffffu, mx0, 1));
        mx0 = fmaxf(mx0, __shfl_xor_sync(0xffffffffu, mx0, 2));
        mx1 = fmaxf(mx1, __shfl_xor_sync(0xffffffffu, mx1, 1));
        mx1 = fmaxf(mx1, __shfl_xor_sync(0xffffffffu, mx1, 2));
        if (t == 0) { sMx[r0 * 2 + wn] = mx0; sMx[r1 * 2 + wn] = mx1; }
        __syncthreads();

        float mn0 = fmaxf(m0v, fmaxf(sMx[r0 * 2], sMx[r0 * 2 + 1]));
        float mn1 = fmaxf(m1v, fmaxf(sMx[r1 * 2], sMx[r1 * 2 + 1]));
        float a0 = fast_exp(m0v - mn0), a1 = fast_exp(m1v - mn1);
        m0v = mn0; m1v = mn1;

        float sum0 = 0.f, sum1 = 0.f;
#pragma unroll
        for (int nt = 0; nt < 4; nt++) {
            float p00 = fast_exp(s[nt][0] - mn0), p01 = fast_exp(s[nt][1] - mn0);
            float p10 = fast_exp(s[nt][2] - mn1), p11 = fast_exp(s[nt][3] - mn1);
            sum0 += p00 + p01; sum1 += p10 + p11;
            int cc = wn * 32 + nt * 8 + 2 * t;
            *(float2*)&sP[r0 * PSTR + cc] =
                make_float2(uaf(f2tf(p00)), uaf(f2tf(p01)));
            *(float2*)&sP[r1 * PSTR + cc] =
                make_float2(uaf(f2tf(p10)), uaf(f2tf(p11)));
        }
        sum0 += __shfl_xor_sync(0xffffffffu, sum0, 1);
        sum0 += __shfl_xor_sync(0xffffffffu, sum0, 2);
        sum1 += __shfl_xor_sync(0xffffffffu, sum1, 1);
        sum1 += __shfl_xor_sync(0xffffffffu, sum1, 2);
        if (t == 0) { sSm[r0 * 2 + wn] = sum0; sSm[r1 * 2 + wn] = sum1; }
        __syncthreads();

        l0 = l0 * a0 + sSm[r0 * 2] + sSm[r0 * 2 + 1];
        l1 = l1 * a1 + sSm[r1 * 2] + sSm[r1 * 2 + 1];
#pragma unroll
        for (int u = 0; u < 10; u++) {
            o[u][0] *= a0; o[u][1] *= a0;
            o[u][2] *= a1; o[u][3] *= a1;
        }

        // ---- O += P @ V ----
#pragma unroll
        for (int ks = 0; ks < 8; ks++) {
            unsigned af[4];
            af[0] = __float_as_uint(sP[r0 * PSTR + ks * 8 + t]);
            af[1] = __float_as_uint(sP[r1 * PSTR + ks * 8 + t]);
            af[2] = __float_as_uint(sP[r0 * PSTR + ks * 8 + t + 4]);
            af[3] = __float_as_uint(sP[r1 * PSTR + ks * 8 + t + 4]);
#pragma unroll
            for (int u = 0; u < 10; u++) {
                int dc = wn * 80 + u * 8 + g;
                unsigned bf[2];
                bf[0] = __float_as_uint(sV[dc * VSTR + ks * 8 + t]);
                bf[1] = __float_as_uint(sV[dc * VSTR + ks * 8 + t + 4]);
                mma8(o[u], af, bf);
            }
        }
    }

    const int b = bh >> 3, h = bh & 7;
    float inv0 = 1.0f / l0, inv1 = 1.0f / l1;
#pragma unroll
    for (int u = 0; u < 10; u++) {
        int cc = h * HDIM + wn * 80 + u * 8 + 2 * t;
        *(float2*)&g_ao[(size_t)(b * SEQ + q0 + r0) * CHN + cc] =
            make_float2(o[u][0] * inv0, o[u][1] * inv0);
        *(float2*)&g_ao[(size_t)(b * SEQ + q0 + r1) * CHN + cc] =
            make_float2(o[u][2] * inv1, o[u][3] * inv1);
    }
}

// ---------------------------------------------------------------------------
// Kernel 3: output projection + bias (tf32 mma)
// ---------------------------------------------------------------------------
__global__ __launch_bounds__(256) void out_gemm(
    const float* __restrict__ W, const float* __restrict__ bias,
    float* __restrict__ out)
{
    __shared__ float As[128 * ASTR];
    __shared__ float Bs[32 * BSTR];

    float c[16][4];
#pragma unroll
    for (int i = 0; i < 16; i++)
#pragma unroll
        for (int j = 0; j < 4; j++) c[i][j] = 0.f;

    gemm_frags(g_ao, W, blockIdx.y * 128, blockIdx.x * 128, c, As, Bs);

    const int lane = threadIdx.x & 31, warp = threadIdx.x >> 5;
    const int g = lane >> 2, t = lane & 3;
    const int wm = warp >> 2, wn = warp & 3;

#pragma unroll
    for (int mt = 0; mt < 4; mt++) {
#pragma unroll
        for (int nt = 0; nt < 4; nt++) {
            int rowb = blockIdx.y * 128 + wm * 64 + mt * 16 + g;
            int col  = blockIdx.x * 128 + wn * 32 + nt * 8 + 2 * t;
            float2 bv = *(const float2*)&bias[col];
#pragma unroll
            for (int half = 0; half < 2; half++) {
                int row = rowb + half * 8;
                float2 v = make_float2(c[mt * 4 + nt][half * 2] + bv.x,
                                       c[mt * 4 + nt][half * 2 + 1] + bv.y);
                *(float2*)&out[(size_t)row * CHN + col] = v;
            }
        }
    }
}

// ---------------------------------------------------------------------------
extern "C" void kernel_launch(void* const* d_in, const int* in_sizes, int n_in,
                              void* d_out, int out_size)
{
    const float* X    = (const float*)d_in[0];
    const float* Wq   = (const float*)d_in[1];
    const float* Wk   = (const float*)d_in[2];
    const float* Wv   = (const float*)d_in[3];
    const float* Wout = (const float*)d_in[4];
    const float* bout = (const float*)d_in[5];
    float* out = (float*)d_out;

    qkv_gemm<<<dim3(CHN / 128, MTOT / 128, 3), 256>>>(X, Wq, Wk, Wv);

    const int smem_bytes =
        (64 * QSTR + HDIM * KSTR + HDIM * VSTR + 64 * PSTR + 256) * (int)sizeof(float);
    cudaFuncSetAttribute(attn_kernel,
                         cudaFuncAttributeMaxDynamicSharedMemorySize, smem_bytes);
    attn_kernel<<<dim3(SEQ / 64, BHN), 256, smem_bytes>>>();

    out_gemm<<<dim3(CHN / 128, MTOT / 128), 256>>>(Wout, bout, out);
}

// round 9
// speedup vs baseline: 3.6550x; 1.5550x over previous
#include <cuda_runtime.h>
#include <math.h>
#include <stdint.h>

#define BATCH 2
#define SEQ   4096
#define CHN   1280
#define HEADS 8
#define HDIM  160
#define BHN   16          // BATCH*HEADS
#define MTOT  8192        // BATCH*SEQ

// Scratch (allocation-free rule: __device__ globals)
__device__ float g_q [(size_t)BHN * SEQ * HDIM];   // [bh][s][d]   tf32, pre-scaled
__device__ float g_kT[(size_t)BHN * HDIM * SEQ];   // [bh][d][s]   tf32
__device__ float g_vT[(size_t)BHN * HDIM * SEQ];   // [bh][d][s]   tf32
__device__ float g_ao[(size_t)MTOT * CHN];         // [b*s][h*d]   tf32
__device__ float g_x [(size_t)MTOT * CHN];         // X rounded to tf32
__device__ float g_wq[(size_t)CHN * CHN];
__device__ float g_wk[(size_t)CHN * CHN];
__device__ float g_wv[(size_t)CHN * CHN];
__device__ float g_wo[(size_t)CHN * CHN];

// ---------------------------------------------------------------------------
// helpers
// ---------------------------------------------------------------------------
__device__ __forceinline__ unsigned f2tf(float x) {
    unsigned r;
    asm("cvt.rna.tf32.f32 %0, %1;" : "=r"(r) : "f"(x));
    return r;
}
__device__ __forceinline__ float uaf(unsigned u) { return __uint_as_float(u); }

__device__ __forceinline__ void mma8(float* c, const unsigned* a, const unsigned* b) {
    asm volatile(
        "mma.sync.aligned.m16n8k8.row.col.f32.tf32.tf32.f32 "
        "{%0,%1,%2,%3}, {%4,%5,%6,%7}, {%8,%9}, {%0,%1,%2,%3};\n"
        : "+f"(c[0]), "+f"(c[1]), "+f"(c[2]), "+f"(c[3])
        : "r"(a[0]), "r"(a[1]), "r"(a[2]), "r"(a[3]), "r"(b[0]), "r"(b[1]));
}

__device__ __forceinline__ void cp16(uint32_t dst, const float* src) {
    asm volatile("cp.async.cg.shared.global [%0], [%1], 16;\n"
                 :: "r"(dst), "l"(src));
}
__device__ __forceinline__ void cp_commit() {
    asm volatile("cp.async.commit_group;\n");
}
__device__ __forceinline__ void cp_wait0() {
    asm volatile("cp.async.wait_group 0;\n" ::: "memory");
}

// exp(x) for x <= 0 on the FMA pipe (no MUFU). |rel err| ~ 2.4e-6.
__device__ __forceinline__ float fast_exp(float x) {
    x = fmaxf(x, -80.0f);
    float y = x * 1.4426950408889634f;
    float t = y + 12582912.0f;
    int   e = __float_as_int(t);
    float n = t - 12582912.0f;
    float f = y - n;
    float p = 1.3333558e-3f;
    p = fmaf(p, f, 9.6181291e-3f);
    p = fmaf(p, f, 5.5504109e-2f);
    p = fmaf(p, f, 2.4022651e-1f);
    p = fmaf(p, f, 6.9314718e-1f);
    p = fmaf(p, f, 1.0f);
    return __int_as_float(__float_as_int(p) + (e << 23));
}

// ---------------------------------------------------------------------------
// Kernel 0: round X + all weights to tf32 once.
// ---------------------------------------------------------------------------
__global__ __launch_bounds__(256) void cvt_all(
    const float* __restrict__ X,  const float* __restrict__ Wq,
    const float* __restrict__ Wk, const float* __restrict__ Wv,
    const float* __restrict__ Wo)
{
    const int NX = MTOT * CHN / 4;   // 2621440 float4
    const int NW = CHN * CHN / 4;    // 409600 float4
    int i = blockIdx.x * 256 + threadIdx.x;
    const float4* s; float4* d; int j;
    if (i < NX)               { s = (const float4*)X;  d = (float4*)g_x;  j = i; }
    else if (i < NX + NW)     { s = (const float4*)Wq; d = (float4*)g_wq; j = i - NX; }
    else if (i < NX + 2 * NW) { s = (const float4*)Wk; d = (float4*)g_wk; j = i - NX - NW; }
    else if (i < NX + 3 * NW) { s = (const float4*)Wv; d = (float4*)g_wv; j = i - NX - 2 * NW; }
    else if (i < NX + 4 * NW) { s = (const float4*)Wo; d = (float4*)g_wo; j = i - NX - 3 * NW; }
    else return;
    float4 v = s[j];
    v.x = uaf(f2tf(v.x)); v.y = uaf(f2tf(v.y));
    v.z = uaf(f2tf(v.z)); v.w = uaf(f2tf(v.w));
    d[j] = v;
}

// ---------------------------------------------------------------------------
// GEMM core: cp.async double-buffered, inputs already tf32.
// warp layout 2(m) x 4(n); warp tile 64x32 -> c[16][4]
// ---------------------------------------------------------------------------
#define ASTR 36
#define BSTR 136
#define ABUF (128 * ASTR)   // 4608 floats
#define BBUF (32 * BSTR)    // 4352 floats
#define GEMM_SMEM ((2 * (ABUF + BBUF)) * 4)   // 71680 bytes

__device__ __forceinline__ void gemm_core(
    const float* __restrict__ A, const float* __restrict__ B,
    int row0, int col0, float c[16][4], float* sm)
{
    float* As = sm;
    float* Bs = sm + 2 * ABUF;
    uint32_t As_u = (uint32_t)__cvta_generic_to_shared(As);
    uint32_t Bs_u = (uint32_t)__cvta_generic_to_shared(Bs);

    const int tid = threadIdx.x;
    const int warp = tid >> 5, lane = tid & 31;
    const int g = lane >> 2, t = lane & 3;
    const int wm = warp >> 2, wn = warp & 3;

    auto issue = [&](int kb, int buf) {
#pragma unroll
        for (int it = 0; it < 4; it++) {
            int lin = it * 256 + tid;
            int ra = lin >> 3, ca = (lin & 7) << 2;
            cp16(As_u + (uint32_t)(buf * ABUF + ra * ASTR + ca) * 4,
                 &A[(size_t)(row0 + ra) * CHN + kb + ca]);
            int rb = lin >> 5, cb = (lin & 31) << 2;
            cp16(Bs_u + (uint32_t)(buf * BBUF + rb * BSTR + cb) * 4,
                 &B[(size_t)(kb + rb) * CHN + col0 + cb]);
        }
        cp_commit();
    };

    issue(0, 0);

    int buf = 0;
    for (int kb = 0; kb < CHN; kb += 32, buf ^= 1) {
        cp_wait0();
        __syncthreads();
        if (kb + 32 < CHN) issue(kb + 32, buf ^ 1);
        const float* Ab = As + buf * ABUF;
        const float* Bb = Bs + buf * BBUF;
#pragma unroll
        for (int ks = 0; ks < 4; ks++) {
            unsigned af[4][4], bf[4][2];
#pragma unroll
            for (int mt = 0; mt < 4; mt++) {
                int r = wm * 64 + mt * 16 + g;
                af[mt][0] = __float_as_uint(Ab[r * ASTR + ks * 8 + t]);
                af[mt][1] = __float_as_uint(Ab[(r + 8) * ASTR + ks * 8 + t]);
                af[mt][2] = __float_as_uint(Ab[r * ASTR + ks * 8 + t + 4]);
                af[mt][3] = __float_as_uint(Ab[(r + 8) * ASTR + ks * 8 + t + 4]);
            }
#pragma unroll
            for (int nt = 0; nt < 4; nt++) {
                int cc = wn * 32 + nt * 8 + g;
                bf[nt][0] = __float_as_uint(Bb[(ks * 8 + t) * BSTR + cc]);
                bf[nt][1] = __float_as_uint(Bb[(ks * 8 + t + 4) * BSTR + cc]);
            }
#pragma unroll
            for (int mt = 0; mt < 4; mt++)
#pragma unroll
                for (int nt = 0; nt < 4; nt++)
                    mma8(c[mt * 4 + nt], af[mt], bf[nt]);
        }
        __syncthreads();
    }
}

// ---------------------------------------------------------------------------
// Kernel 1: fused QKV projection. Outputs written tf32 (Q pre-scaled).
// ---------------------------------------------------------------------------
__global__ __launch_bounds__(256, 2) void qkv_gemm()
{
    extern __shared__ float sm[];
    float c[16][4];
#pragma unroll
    for (int i = 0; i < 16; i++)
#pragma unroll
        for (int j = 0; j < 4; j++) c[i][j] = 0.f;

    const float* __restrict__ W =
        (blockIdx.z == 0) ? g_wq : (blockIdx.z == 1 ? g_wk : g_wv);
    gemm_core(g_x, W, blockIdx.y * 128, blockIdx.x * 128, c, sm);

    const int lane = threadIdx.x & 31, warp = threadIdx.x >> 5;
    const int g = lane >> 2, t = lane & 3;
    const int wm = warp >> 2, wn = warp & 3;
    const float scale = 0.07905694150420949f;  // 1/sqrt(160)

#pragma unroll
    for (int mt = 0; mt < 4; mt++) {
#pragma unroll
        for (int nt = 0; nt < 4; nt++) {
            int rowb = blockIdx.y * 128 + wm * 64 + mt * 16 + g;
            int col  = blockIdx.x * 128 + wn * 32 + nt * 8 + 2 * t;
            if (blockIdx.z == 0) {
#pragma unroll
                for (int half = 0; half < 2; half++) {
                    int row = rowb + half * 8;
                    int b = row >> 12, s = row & (SEQ - 1);
                    int h = col / HDIM, d = col - h * HDIM;
                    float2 v = make_float2(
                        uaf(f2tf(c[mt * 4 + nt][half * 2] * scale)),
                        uaf(f2tf(c[mt * 4 + nt][half * 2 + 1] * scale)));
                    *(float2*)&g_q[((size_t)(b * HEADS + h) * SEQ + s) * HDIM + d] = v;
                }
            } else {
                float* __restrict__ G = (blockIdx.z == 1) ? g_kT : g_vT;
#pragma unroll
                for (int i = 0; i < 4; i++) {
                    int row = rowb + (i >> 1) * 8;
                    int cj  = col + (i & 1);
                    int b = row >> 12, s = row & (SEQ - 1);
                    int h = cj / HDIM, d = cj - h * HDIM;
                    G[((size_t)(b * HEADS + h) * HDIM + d) * SEQ + s] =
                        uaf(f2tf(c[mt * 4 + nt][i]));
                }
            }
        }
    }
}

// ---------------------------------------------------------------------------
// Kernel 2: flash attention. Q in registers; cp.async double-buffered K/V.
// Warp layout: 4(m) x 2(n). S: warp 16x32. PV: warp 16x80.
// ---------------------------------------------------------------------------
#define KSTR 72
#define VSTR 68
#define PSTR 68
#define QSTR 164
#define KBUF (HDIM * KSTR)   // 11520
#define VBUF (HDIM * VSTR)   // 10880
// smem floats: sK[2*KBUF] | sV[2*VBUF] | sP[64*PSTR] | sMx[128] | sSm[128]
#define ATTN_SMEM ((2 * KBUF + 2 * VBUF + 64 * PSTR + 256) * 4)   // 197632 B

__global__ __launch_bounds__(256, 1) void attn_kernel()
{
    extern __shared__ float smem[];
    float* sK  = smem;
    float* sV  = smem + 2 * KBUF;
    float* sP  = sV + 2 * VBUF;
    float* sMx = sP + 64 * PSTR;
    float* sSm = sMx + 128;
    uint32_t smem_u = (uint32_t)__cvta_generic_to_shared(smem);

    const int bh = blockIdx.y;
    const int q0 = blockIdx.x * 64;
    const int tid = threadIdx.x, warp = tid >> 5, lane = tid & 31;
    const int g = lane >> 2, t = lane & 3;
    const int wm = warp >> 1, wn = warp & 1;
    const int r0 = wm * 16 + g, r1 = r0 + 8;

    // ---- stage Q (already tf32, pre-scaled) through smem, frags -> regs ----
    const float* __restrict__ Qg = g_q + ((size_t)bh * SEQ + q0) * HDIM;
#pragma unroll
    for (int it = 0; it < 10; it++) {
        int lin = it * 256 + tid;            // 2560 float4
        int r = lin / 40, c4 = (lin % 40) * 4;
        *(float4*)&smem[r * QSTR + c4] = *(const float4*)&Qg[(size_t)r * HDIM + c4];
    }
    __syncthreads();
    unsigned qf[20][4];
#pragma unroll
    for (int ks = 0; ks < 20; ks++) {
        qf[ks][0] = __float_as_uint(smem[r0 * QSTR + ks * 8 + t]);
        qf[ks][1] = __float_as_uint(smem[r1 * QSTR + ks * 8 + t]);
        qf[ks][2] = __float_as_uint(smem[r0 * QSTR + ks * 8 + t + 4]);
        qf[ks][3] = __float_as_uint(smem[r1 * QSTR + ks * 8 + t + 4]);
    }
    __syncthreads();

    const float* __restrict__ Kg = g_kT + (size_t)bh * HDIM * SEQ;
    const float* __restrict__ Vg = g_vT + (size_t)bh * HDIM * SEQ;

    auto issue_tile = [&](int kt, int buf) {
#pragma unroll
        for (int it = 0; it < 10; it++) {
            int lin = it * 256 + tid;        // 2560 float4 each for K and V
            int d = lin >> 4, c4 = (lin & 15) << 2;
            cp16(smem_u + (uint32_t)(buf * KBUF + d * KSTR + c4) * 4,
                 &Kg[(size_t)d * SEQ + kt + c4]);
            cp16(smem_u + (uint32_t)(2 * KBUF + buf * VBUF + d * VSTR + c4) * 4,
                 &Vg[(size_t)d * SEQ + kt + c4]);
        }
        cp_commit();
    };
    issue_tile(0, 0);

    float o[10][4];
#pragma unroll
    for (int u = 0; u < 10; u++)
#pragma unroll
        for (int j = 0; j < 4; j++) o[u][j] = 0.f;
    float m0v = -1e30f, m1v = -1e30f, l0 = 0.f, l1 = 0.f;

    for (int idx = 0; idx < 64; idx++) {
        const int buf = idx & 1;
        cp_wait0();
        __syncthreads();                       // tile ready + prev PV done
        if (idx + 1 < 64) issue_tile((idx + 1) * 64, buf ^ 1);
        const float* Kb = sK + buf * KBUF;
        const float* Vb = sV + buf * VBUF;

        // ---- S = Q @ K^T ----
        float s[4][4];
#pragma unroll
        for (int nt = 0; nt < 4; nt++)
#pragma unroll
            for (int j = 0; j < 4; j++) s[nt][j] = 0.f;

#pragma unroll
        for (int ks = 0; ks < 20; ks++) {
#pragma unroll
            for (int nt = 0; nt < 4; nt++) {
                int cc = wn * 32 + nt * 8 + g;
                unsigned bf[2];
                bf[0] = __float_as_uint(Kb[(ks * 8 + t) * KSTR + cc]);
                bf[1] = __float_as_uint(Kb[(ks * 8 + t + 4) * KSTR + cc]);
                mma8(s[nt], qf[ks], bf);
            }
        }

        // ---- online softmax ----
        float mx0 = fmaxf(fmaxf(s[0][0], s[0][1]), fmaxf(s[1][0], s[1][1]));
        mx0 = fmaxf(mx0, fmaxf(fmaxf(s[2][0], s[2][1]), fmaxf(s[3][0], s[3][1])));
        float mx1 = fmaxf(fmaxf(s[0][2], s[0][3]), fmaxf(s[1][2], s[1][3]));
        mx1 = fmaxf(mx1, fmaxf(fmaxf(s[2][2], s[2][3]), fmaxf(s[3][2], s[3][3])));
        mx0 = fmaxf(mx0, __shfl_xor_sync(0xffffffffu, mx0, 1));
        mx0 = fmaxf(mx0, __shfl_xor_sync(0xffffffffu, mx0, 2));
        mx1 = fmaxf(mx1, __shfl_xor_sync(0xffffffffu, mx1, 1));
        mx1 = fmaxf(mx1, __shfl_xor_sync(0xffffffffu, mx1, 2));
        if (t == 0) { sMx[r0 * 2 + wn] = mx0; sMx[r1 * 2 + wn] = mx1; }
        __syncthreads();

        float mn0 = fmaxf(m0v, fmaxf(sMx[r0 * 2], sMx[r0 * 2 + 1]));
        float mn1 = fmaxf(m1v, fmaxf(sMx[r1 * 2], sMx[r1 * 2 + 1]));
        float a0 = fast_exp(m0v - mn0), a1 = fast_exp(m1v - mn1);
        m0v = mn0; m1v = mn1;

        float sum0 = 0.f, sum1 = 0.f;
#pragma unroll
        for (int nt = 0; nt < 4; nt++) {
            float p00 = fast_exp(s[nt][0] - mn0), p01 = fast_exp(s[nt][1] - mn0);
            float p10 = fast_exp(s[nt][2] - mn1), p11 = fast_exp(s[nt][3] - mn1);
            sum0 += p00 + p01; sum1 += p10 + p11;
            int cc = wn * 32 + nt * 8 + 2 * t;
            *(float2*)&sP[r0 * PSTR + cc] =
                make_float2(uaf(f2tf(p00)), uaf(f2tf(p01)));
            *(float2*)&sP[r1 * PSTR + cc] =
                make_float2(uaf(f2tf(p10)), uaf(f2tf(p11)));
        }
        sum0 += __shfl_xor_sync(0xffffffffu, sum0, 1);
        sum0 += __shfl_xor_sync(0xffffffffu, sum0, 2);
        sum1 += __shfl_xor_sync(0xffffffffu, sum1, 1);
        sum1 += __shfl_xor_sync(0xffffffffu, sum1, 2);
        if (t == 0) { sSm[r0 * 2 + wn] = sum0; sSm[r1 * 2 + wn] = sum1; }
        __syncthreads();

        l0 = l0 * a0 + sSm[r0 * 2] + sSm[r0 * 2 + 1];
        l1 = l1 * a1 + sSm[r1 * 2] + sSm[r1 * 2 + 1];
#pragma unroll
        for (int u = 0; u < 10; u++) {
            o[u][0] *= a0; o[u][1] *= a0;
            o[u][2] *= a1; o[u][3] *= a1;
        }

        // ---- O += P @ V ----
#pragma unroll
        for (int ks = 0; ks < 8; ks++) {
            unsigned af[4];
            af[0] = __float_as_uint(sP[r0 * PSTR + ks * 8 + t]);
            af[1] = __float_as_uint(sP[r1 * PSTR + ks * 8 + t]);
            af[2] = __float_as_uint(sP[r0 * PSTR + ks * 8 + t + 4]);
            af[3] = __float_as_uint(sP[r1 * PSTR + ks * 8 + t + 4]);
#pragma unroll
            for (int u = 0; u < 10; u++) {
                int dc = wn * 80 + u * 8 + g;
                unsigned bf[2];
                bf[0] = __float_as_uint(Vb[dc * VSTR + ks * 8 + t]);
                bf[1] = __float_as_uint(Vb[dc * VSTR + ks * 8 + t + 4]);
                mma8(o[u], af, bf);
            }
        }
    }

    const int b = bh >> 3, h = bh & 7;
    float inv0 = 1.0f / l0, inv1 = 1.0f / l1;
#pragma unroll
    for (int u = 0; u < 10; u++) {
        int cc = h * HDIM + wn * 80 + u * 8 + 2 * t;
        *(float2*)&g_ao[(size_t)(b * SEQ + q0 + r0) * CHN + cc] =
            make_float2(uaf(f2tf(o[u][0] * inv0)), uaf(f2tf(o[u][1] * inv0)));
        *(float2*)&g_ao[(size_t)(b * SEQ + q0 + r1) * CHN + cc] =
            make_float2(uaf(f2tf(o[u][2] * inv1)), uaf(f2tf(o[u][3] * inv1)));
    }
}

// ---------------------------------------------------------------------------
// Kernel 3: output projection + bias (inputs already tf32)
// ---------------------------------------------------------------------------
__global__ __launch_bounds__(256, 2) void out_gemm(
    const float* __restrict__ bias, float* __restrict__ out)
{
    extern __shared__ float sm[];
    float c[16][4];
#pragma unroll
    for (int i = 0; i < 16; i++)
#pragma unroll
        for (int j = 0; j < 4; j++) c[i][j] = 0.f;

    gemm_core(g_ao, g_wo, blockIdx.y * 128, blockIdx.x * 128, c, sm);

    const int lane = threadIdx.x & 31, warp = threadIdx.x >> 5;
    const int g = lane >> 2, t = lane & 3;
    const int wm = warp >> 2, wn = warp & 3;

#pragma unroll
    for (int mt = 0; mt < 4; mt++) {
#pragma unroll
        for (int nt = 0; nt < 4; nt++) {
            int rowb = blockIdx.y * 128 + wm * 64 + mt * 16 + g;
            int col  = blockIdx.x * 128 + wn * 32 + nt * 8 + 2 * t;
            float2 bv = *(const float2*)&bias[col];
#pragma unroll
            for (int half = 0; half < 2; half++) {
                int row = rowb + half * 8;
                float2 v = make_float2(c[mt * 4 + nt][half * 2] + bv.x,
                                       c[mt * 4 + nt][half * 2 + 1] + bv.y);
                *(float2*)&out[(size_t)row * CHN + col] = v;
            }
        }
    }
}

// ---------------------------------------------------------------------------
extern "C" void kernel_launch(void* const* d_in, const int* in_sizes, int n_in,
                              void* d_out, int out_size)
{
    const float* X    = (const float*)d_in[0];
    const float* Wq   = (const float*)d_in[1];
    const float* Wk   = (const float*)d_in[2];
    const float* Wv   = (const float*)d_in[3];
    const float* Wout = (const float*)d_in[4];
    const float* bout = (const float*)d_in[5];
    float* out = (float*)d_out;

    const int NX = MTOT * CHN / 4, NW = CHN * CHN / 4;
    cvt_all<<<(NX + 4 * NW + 255) / 256, 256>>>(X, Wq, Wk, Wv, Wout);

    cudaFuncSetAttribute(qkv_gemm,
                         cudaFuncAttributeMaxDynamicSharedMemorySize, GEMM_SMEM);
    qkv_gemm<<<dim3(CHN / 128, MTOT / 128, 3), 256, GEMM_SMEM>>>();

    cudaFuncSetAttribute(attn_kernel,
                         cudaFuncAttributeMaxDynamicSharedMemorySize, ATTN_SMEM);
    attn_kernel<<<dim3(SEQ / 64, BHN), 256, ATTN_SMEM>>>();

    cudaFuncSetAttribute(out_gemm,
                         cudaFuncAttributeMaxDynamicSharedMemorySize, GEMM_SMEM);
    out_gemm<<<dim3(CHN / 128, MTOT / 128), 256, GEMM_SMEM>>>(bout, out);
}

// round 13
// speedup vs baseline: 4.0409x; 1.1056x over previous
#include <cuda_runtime.h>
#include <math.h>
#include <stdint.h>

#define BATCH 2
#define SEQ   4096
#define CHN   1280
#define HEADS 8
#define HDIM  160
#define BHN   16          // BATCH*HEADS
#define MTOT  8192        // BATCH*SEQ

// Scratch (allocation-free rule: __device__ globals)
__device__ float g_q [(size_t)BHN * SEQ * HDIM];   // [bh][s][d] tf32, pre-scaled
__device__ float g_kT[(size_t)BHN * HDIM * SEQ];   // [bh][d/8][s][8] pair-interleaved
__device__ float g_vT[(size_t)BHN * HDIM * SEQ];   // [bh][d][s/8][8] pair-interleaved
__device__ float g_ao[(size_t)MTOT * CHN];         // [row][col'] col-permuted tf32
__device__ float g_x [(size_t)MTOT * CHN];         // [row][col'] col-permuted tf32
__device__ float g_wq[(size_t)CHN * CHN];          // [k/8][n][8] pair-interleaved
__device__ float g_wk[(size_t)CHN * CHN];
__device__ float g_wv[(size_t)CHN * CHN];
__device__ float g_wo[(size_t)CHN * CHN];

// ---------------------------------------------------------------------------
// helpers
// ---------------------------------------------------------------------------
__device__ __forceinline__ unsigned f2tf(float x) {
    unsigned r;
    asm("cvt.rna.tf32.f32 %0, %1;" : "=r"(r) : "f"(x));
    return r;
}
__device__ __forceinline__ float uaf(unsigned u) { return __uint_as_float(u); }
__device__ __forceinline__ int perm8(int kk) { return ((kk & 3) << 1) | (kk >> 2); }

__device__ __forceinline__ void mma8(float* c, const unsigned* a, const unsigned* b) {
    asm volatile(
        "mma.sync.aligned.m16n8k8.row.col.f32.tf32.tf32.f32 "
        "{%0,%1,%2,%3}, {%4,%5,%6,%7}, {%8,%9}, {%0,%1,%2,%3};\n"
        : "+f"(c[0]), "+f"(c[1]), "+f"(c[2]), "+f"(c[3])
        : "r"(a[0]), "r"(a[1]), "r"(a[2]), "r"(a[3]), "r"(b[0]), "r"(b[1]));
}
// a-pair fragments as float2: lo = k=t, hi = k=t+4
__device__ __forceinline__ void mma8p(float* c, float2 a0, float2 a1, float2 b) {
    unsigned af[4] = { __float_as_uint(a0.x), __float_as_uint(a1.x),
                       __float_as_uint(a0.y), __float_as_uint(a1.y) };
    unsigned bf[2] = { __float_as_uint(b.x), __float_as_uint(b.y) };
    mma8(c, af, bf);
}

__device__ __forceinline__ void cp16(uint32_t dst, const float* src) {
    asm volatile("cp.async.cg.shared.global [%0], [%1], 16;\n"
                 :: "r"(dst), "l"(src));
}
__device__ __forceinline__ void cp_commit() {
    asm volatile("cp.async.commit_group;\n");
}
__device__ __forceinline__ void cp_wait0() {
    asm volatile("cp.async.wait_group 0;\n" ::: "memory");
}

// exp(x) for x <= 0 on the FMA pipe (no MUFU). |rel err| ~ 2.4e-6.
__device__ __forceinline__ float fast_exp(float x) {
    x = fmaxf(x, -80.0f);
    float y = x * 1.4426950408889634f;
    float t = y + 12582912.0f;
    int   e = __float_as_int(t);
    float n = t - 12582912.0f;
    float f = y - n;
    float p = 1.3333558e-3f;
    p = fmaf(p, f, 9.6181291e-3f);
    p = fmaf(p, f, 5.5504109e-2f);
    p = fmaf(p, f, 2.4022651e-1f);
    p = fmaf(p, f, 6.9314718e-1f);
    p = fmaf(p, f, 1.0f);
    return __int_as_float(__float_as_int(p) + (e << 23));
}

// ---------------------------------------------------------------------------
// Kernel 0: round X + weights to tf32, writing mma-friendly layouts.
// X/g_ao-style: column c -> (c & ~7) + perm8(c & 7)
// W: [k][n] -> g_w2[(k>>3)*(CHN*8) + n*8 + perm8(k&7)]
// ---------------------------------------------------------------------------
__global__ __launch_bounds__(256) void cvt_all(
    const float* __restrict__ X,  const float* __restrict__ Wq,
    const float* __restrict__ Wk, const float* __restrict__ Wv,
    const float* __restrict__ Wo)
{
    const int NX = MTOT * CHN / 4;
    const int NW = CHN * CHN / 4;
    int i = blockIdx.x * 256 + threadIdx.x;
    if (i < NX) {
        int base = i * 4;
        int row = base / CHN, c = base - row * CHN;
        float4 v = *(const float4*)&X[(size_t)row * CHN + c];
        float* d = &g_x[(size_t)row * CHN + (c & ~7) + ((c >> 2) & 1)];
        d[0] = uaf(f2tf(v.x)); d[2] = uaf(f2tf(v.y));
        d[4] = uaf(f2tf(v.z)); d[6] = uaf(f2tf(v.w));
        return;
    }
    i -= NX;
    if (i >= 4 * NW) return;
    const float* s; float* d2;
    if (i < NW)          { s = Wq; d2 = g_wq; }
    else if (i < 2 * NW) { s = Wk; d2 = g_wk; i -= NW; }
    else if (i < 3 * NW) { s = Wv; d2 = g_wv; i -= 2 * NW; }
    else                 { s = Wo; d2 = g_wo; i -= 3 * NW; }
    int base = i * 4;
    int k = base / CHN, n = base - k * CHN;
    float4 v = *(const float4*)&s[(size_t)k * CHN + n];
    float* d = &d2[(size_t)(k >> 3) * (CHN * 8) + (size_t)n * 8 + perm8(k & 7)];
    d[0] = uaf(f2tf(v.x)); d[8] = uaf(f2tf(v.y));
    d[16] = uaf(f2tf(v.z)); d[24] = uaf(f2tf(v.w));
}

// ---------------------------------------------------------------------------
// GEMM core: cp.async double-buffered; A col-permuted, B in w2 layout.
// warp layout 2(m) x 4(n); warp tile 64x32 -> c[16][4]
// ---------------------------------------------------------------------------
#define ASTR 40
#define ABUF (128 * ASTR)   // 5120 floats
#define BBUF (32 * 128)     // 4096 floats: [ks(4)][n(128)][8]
#define GEMM_SMEM ((2 * (ABUF + BBUF)) * 4)   // 73728 bytes

__device__ __forceinline__ void gemm_core(
    const float* __restrict__ A, const float* __restrict__ B2,
    int row0, int col0, float c[16][4], float* sm)
{
    float* As = sm;
    float* Bs = sm + 2 * ABUF;
    uint32_t As_u = (uint32_t)__cvta_generic_to_shared(As);
    uint32_t Bs_u = (uint32_t)__cvta_generic_to_shared(Bs);

    const int tid = threadIdx.x;
    const int warp = tid >> 5, lane = tid & 31;
    const int g = lane >> 2, t = lane & 3;
    const int wm = warp >> 2, wn = warp & 3;

    auto issue = [&](int kb, int buf) {
        int kblk0 = kb >> 3;
#pragma unroll
        for (int it = 0; it < 4; it++) {
            int lin = it * 256 + tid;
            int ra = lin >> 3, ca = (lin & 7) << 2;
            cp16(As_u + (uint32_t)(buf * ABUF + ra * ASTR + ca) * 4,
                 &A[(size_t)(row0 + ra) * CHN + kb + ca]);
            int ks = lin >> 8, nn = (lin >> 1) & 127, p4 = (lin & 1) << 2;
            cp16(Bs_u + (uint32_t)(buf * BBUF + lin * 4) * 4,
                 &B2[(size_t)(kblk0 + ks) * (CHN * 8) + (size_t)(col0 + nn) * 8 + p4]);
        }
        cp_commit();
    };

    issue(0, 0);

    int buf = 0;
    for (int kb = 0; kb < CHN; kb += 32, buf ^= 1) {
        cp_wait0();
        __syncthreads();
        if (kb + 32 < CHN) issue(kb + 32, buf ^ 1);
        const float* Ab = As + buf * ABUF;
        const float* Bb = Bs + buf * BBUF;
#pragma unroll
        for (int ks = 0; ks < 4; ks++) {
            float2 a0[4], a1[4], bfr[4];
#pragma unroll
            for (int mt = 0; mt < 4; mt++) {
                int r = wm * 64 + mt * 16 + g;
                a0[mt] = *(const float2*)&Ab[r * ASTR + ks * 8 + 2 * t];
                a1[mt] = *(const float2*)&Ab[(r + 8) * ASTR + ks * 8 + 2 * t];
            }
#pragma unroll
            for (int nt = 0; nt < 4; nt++) {
                int cc = wn * 32 + nt * 8 + g;
                bfr[nt] = *(const float2*)&Bb[ks * 1024 + cc * 8 + 2 * t];
            }
#pragma unroll
            for (int mt = 0; mt < 4; mt++)
#pragma unroll
                for (int nt = 0; nt < 4; nt++)
                    mma8p(c[mt * 4 + nt], a0[mt], a1[mt], bfr[nt]);
        }
        __syncthreads();
    }
}

// ---------------------------------------------------------------------------
// Kernel 1: fused QKV projection. Epilogues write attention-ready layouts.
// ---------------------------------------------------------------------------
__global__ __launch_bounds__(256, 2) void qkv_gemm()
{
    extern __shared__ float sm[];
    float c[16][4];
#pragma unroll
    for (int i = 0; i < 16; i++)
#pragma unroll
        for (int j = 0; j < 4; j++) c[i][j] = 0.f;

    const float* __restrict__ W =
        (blockIdx.z == 0) ? g_wq : (blockIdx.z == 1 ? g_wk : g_wv);
    gemm_core(g_x, W, blockIdx.y * 128, blockIdx.x * 128, c, sm);

    const int lane = threadIdx.x & 31, warp = threadIdx.x >> 5;
    const int g = lane >> 2, t = lane & 3;
    const int wm = warp >> 2, wn = warp & 3;
    const float scale = 0.07905694150420949f;  // 1/sqrt(160)

#pragma unroll
    for (int mt = 0; mt < 4; mt++) {
#pragma unroll
        for (int nt = 0; nt < 4; nt++) {
            int rowb = blockIdx.y * 128 + wm * 64 + mt * 16 + g;
            int col  = blockIdx.x * 128 + wn * 32 + nt * 8 + 2 * t;
            if (blockIdx.z == 0) {
#pragma unroll
                for (int half = 0; half < 2; half++) {
                    int row = rowb + half * 8;
                    int b = row >> 12, s = row & (SEQ - 1);
                    int h = col / HDIM, d = col - h * HDIM;
                    float2 v = make_float2(
                        uaf(f2tf(c[mt * 4 + nt][half * 2] * scale)),
                        uaf(f2tf(c[mt * 4 + nt][half * 2 + 1] * scale)));
                    *(float2*)&g_q[((size_t)(b * HEADS + h) * SEQ + s) * HDIM + d] = v;
                }
            } else if (blockIdx.z == 1) {
                // K: [bh][d>>3][s][8], inner perm8(d&7)
#pragma unroll
                for (int i = 0; i < 4; i++) {
                    int row = rowb + (i >> 1) * 8;
                    int cj  = col + (i & 1);
                    int b = row >> 12, s = row & (SEQ - 1);
                    int h = cj / HDIM, d = cj - h * HDIM;
                    int bh = b * HEADS + h;
                    g_kT[(((size_t)(bh * 20 + (d >> 3))) * SEQ + s) * 8 + perm8(d & 7)] =
                        uaf(f2tf(c[mt * 4 + nt][i]));
                }
            } else {
                // V: [bh][d][s>>3][8], inner perm8(s&7)
#pragma unroll
                for (int i = 0; i < 4; i++) {
                    int row = rowb + (i >> 1) * 8;
                    int cj  = col + (i & 1);
                    int b = row >> 12, s = row & (SEQ - 1);
                    int h = cj / HDIM, d = cj - h * HDIM;
                    int bh = b * HEADS + h;
                    g_vT[(((size_t)(bh * HDIM + d)) * 512 + (s >> 3)) * 8 + perm8(s & 7)] =
                        uaf(f2tf(c[mt * 4 + nt][i]));
                }
            }
        }
    }
}

// ---------------------------------------------------------------------------
// Kernel 2: flash attention. Q in regs; pair-interleaved K/V/P, LDS.64 frags.
// Warp layout: 4(m) x 2(n). S: warp 16x32. PV: warp 16x80.
// ---------------------------------------------------------------------------
#define KBUF 10240          // [ks(20)][key(64)][8]
#define VSTRD 72            // [d(160)][ksb(8)*8 + pad]
#define VBUF (HDIM * VSTRD) // 11520
#define PSTRD 72
#define PBUF (64 * PSTRD)   // 4608
#define QSTR 164
// floats: sK[2*KBUF] | sV[2*VBUF] | sP | sMx[128] | sSm[128]
#define ATTN_SMEM ((2 * KBUF + 2 * VBUF + PBUF + 256) * 4)   // 193536 B

__global__ __launch_bounds__(256, 1) void attn_kernel()
{
    extern __shared__ float smem[];
    float* sK  = smem;
    float* sV  = smem + 2 * KBUF;
    float* sP  = sV + 2 * VBUF;
    float* sMx = sP + PBUF;
    float* sSm = sMx + 128;
    uint32_t smem_u = (uint32_t)__cvta_generic_to_shared(smem);

    const int bh = blockIdx.y;
    const int q0 = blockIdx.x * 64;
    const int tid = threadIdx.x, warp = tid >> 5, lane = tid & 31;
    const int g = lane >> 2, t = lane & 3;
    const int wm = warp >> 1, wn = warp & 1;
    const int r0 = wm * 16 + g, r1 = r0 + 8;

    // ---- stage Q (tf32, pre-scaled) through smem, frags -> regs ----
    const float* __restrict__ Qg = g_q + ((size_t)bh * SEQ + q0) * HDIM;
#pragma unroll
    for (int it = 0; it < 10; it++) {
        int lin = it * 256 + tid;            // 2560 float4
        int r = lin / 40, c4 = (lin % 40) * 4;
        *(float4*)&smem[r * QSTR + c4] = *(const float4*)&Qg[(size_t)r * HDIM + c4];
    }
    __syncthreads();
    unsigned qf[20][4];
#pragma unroll
    for (int ks = 0; ks < 20; ks++) {
        qf[ks][0] = __float_as_uint(smem[r0 * QSTR + ks * 8 + t]);
        qf[ks][1] = __float_as_uint(smem[r1 * QSTR + ks * 8 + t]);
        qf[ks][2] = __float_as_uint(smem[r0 * QSTR + ks * 8 + t + 4]);
        qf[ks][3] = __float_as_uint(smem[r1 * QSTR + ks * 8 + t + 4]);
    }
    __syncthreads();

    const float* __restrict__ Kg = g_kT + (size_t)bh * HDIM * SEQ;  // [dblk][s][8]
    const float* __restrict__ Vg = g_vT + (size_t)bh * HDIM * SEQ;  // [d][sblk][8]

    auto issue_tile = [&](int kt, int buf) {
#pragma unroll
        for (int it = 0; it < 10; it++) {
            int lin = it * 256 + tid;
            // K: [dblk][key][8] contiguous both sides
            int dblk = lin >> 7, rem = lin & 127;
            int key = rem >> 1, p4 = (lin & 1) << 2;
            cp16(smem_u + (uint32_t)(buf * KBUF + lin * 4) * 4,
                 &Kg[(size_t)dblk * (SEQ * 8) + (size_t)(kt + key) * 8 + p4]);
            // V: per-d array is 4096 floats ([sblk(512)][8]); tile kt spans
            // [kt, kt+64) contiguous floats within it.
            int d = lin >> 4, c4 = (lin & 15) << 2;
            cp16(smem_u + (uint32_t)(2 * KBUF + buf * VBUF + d * VSTRD + c4) * 4,
                 &Vg[(size_t)d * 4096 + kt + c4]);
        }
        cp_commit();
    };
    issue_tile(0, 0);

    float o[10][4];
#pragma unroll
    for (int u = 0; u < 10; u++)
#pragma unroll
        for (int j = 0; j < 4; j++) o[u][j] = 0.f;
    float m0v = -1e30f, m1v = -1e30f, l0 = 0.f, l1 = 0.f;

    // perm positions for P stores: key kk=2t -> pp0, kk=2t+1 -> pp0+2
    const int pp0 = ((2 * t) & 3) * 2 + (t >> 1);

    for (int idx = 0; idx < 64; idx++) {
        const int buf = idx & 1;
        cp_wait0();
        __syncthreads();                       // tile ready + prev PV done
        if (idx + 1 < 64) issue_tile((idx + 1) * 64, buf ^ 1);
        const float* Kb = sK + buf * KBUF;
        const float* Vb = sV + buf * VBUF;

        // ---- S = Q @ K^T ----
        float s[4][4];
#pragma unroll
        for (int nt = 0; nt < 4; nt++)
#pragma unroll
            for (int j = 0; j < 4; j++) s[nt][j] = 0.f;

#pragma unroll
        for (int ks = 0; ks < 20; ks++) {
#pragma unroll
            for (int nt = 0; nt < 4; nt++) {
                int cc = wn * 32 + nt * 8 + g;
                float2 b = *(const float2*)&Kb[ks * 512 + cc * 8 + 2 * t];
                unsigned bf[2] = { __float_as_uint(b.x), __float_as_uint(b.y) };
                mma8(s[nt], qf[ks], bf);
            }
        }

        // ---- online softmax ----
        float mx0 = fmaxf(fmaxf(s[0][0], s[0][1]), fmaxf(s[1][0], s[1][1]));
        mx0 = fmaxf(mx0, fmaxf(fmaxf(s[2][0], s[2][1]), fmaxf(s[3][0], s[3][1])));
        float mx1 = fmaxf(fmaxf(s[0][2], s[0][3]), fmaxf(s[1][2], s[1][3]));
        mx1 = fmaxf(mx1, fmaxf(fmaxf(s[2][2], s[2][3]), fmaxf(s[3][2], s[3][3])));
        mx0 = fmaxf(mx0, __shfl_xor_sync(0xffffffffu, mx0, 1));
        mx0 = fmaxf(mx0, __shfl_xor_sync(0xffffffffu, mx0, 2));
        mx1 = fmaxf(mx1, __shfl_xor_sync(0xffffffffu, mx1, 1));
        mx1 = fmaxf(mx1, __shfl_xor_sync(0xffffffffu, mx1, 2));
        if (t == 0) { sMx[r0 * 2 + wn] = mx0; sMx[r1 * 2 + wn] = mx1; }
        __syncthreads();

        float mn0 = fmaxf(m0v, fmaxf(sMx[r0 * 2], sMx[r0 * 2 + 1]));
        float mn1 = fmaxf(m1v, fmaxf(sMx[r1 * 2], sMx[r1 * 2 + 1]));
        float a0 = fast_exp(m0v - mn0), a1 = fast_exp(m1v - mn1);
        m0v = mn0; m1v = mn1;

        float sum0 = 0.f, sum1 = 0.f;
#pragma unroll
        for (int nt = 0; nt < 4; nt++) {
            float p00 = fast_exp(s[nt][0] - mn0), p01 = fast_exp(s[nt][1] - mn0);
            float p10 = fast_exp(s[nt][2] - mn1), p11 = fast_exp(s[nt][3] - mn1);
            sum0 += p00 + p01; sum1 += p10 + p11;
            int kb8 = (wn * 4 + nt) * 8;       // key-block base in P layout
            sP[r0 * PSTRD + kb8 + pp0]     = uaf(f2tf(p00));
            sP[r0 * PSTRD + kb8 + pp0 + 2] = uaf(f2tf(p01));
            sP[r1 * PSTRD + kb8 + pp0]     = uaf(f2tf(p10));
            sP[r1 * PSTRD + kb8 + pp0 + 2] = uaf(f2tf(p11));
        }
        sum0 += __shfl_xor_sync(0xffffffffu, sum0, 1);
        sum0 += __shfl_xor_sync(0xffffffffu, sum0, 2);
        sum1 += __shfl_xor_sync(0xffffffffu, sum1, 1);
        sum1 += __shfl_xor_sync(0xffffffffu, sum1, 2);
        if (t == 0) { sSm[r0 * 2 + wn] = sum0; sSm[r1 * 2 + wn] = sum1; }
        __syncthreads();

        l0 = l0 * a0 + sSm[r0 * 2] + sSm[r0 * 2 + 1];
        l1 = l1 * a1 + sSm[r1 * 2] + sSm[r1 * 2 + 1];
#pragma unroll
        for (int u = 0; u < 10; u++) {
            o[u][0] *= a0; o[u][1] *= a0;
            o[u][2] *= a1; o[u][3] *= a1;
        }

        // ---- O += P @ V ----
#pragma unroll
        for (int ks = 0; ks < 8; ks++) {
            float2 pa0 = *(const float2*)&sP[r0 * PSTRD + ks * 8 + 2 * t];
            float2 pa1 = *(const float2*)&sP[r1 * PSTRD + ks * 8 + 2 * t];
#pragma unroll
            for (int u = 0; u < 10; u++) {
                int dc = wn * 80 + u * 8 + g;
                float2 b = *(const float2*)&Vb[dc * VSTRD + ks * 8 + 2 * t];
                mma8p(o[u], pa0, pa1, b);
            }
        }
    }

    // epilogue: write g_ao with column-permuted layout (for out_gemm A)
    const int b = bh >> 3, h = bh & 7;
    float inv0 = 1.0f / l0, inv1 = 1.0f / l1;
#pragma unroll
    for (int u = 0; u < 10; u++) {
        int cb = h * HDIM + wn * 80 + u * 8;       // 8-aligned block base
        size_t ro0 = (size_t)(b * SEQ + q0 + r0) * CHN + cb;
        size_t ro1 = (size_t)(b * SEQ + q0 + r1) * CHN + cb;
        g_ao[ro0 + pp0]     = uaf(f2tf(o[u][0] * inv0));
        g_ao[ro0 + pp0 + 2] = uaf(f2tf(o[u][1] * inv0));
        g_ao[ro1 + pp0]     = uaf(f2tf(o[u][2] * inv1));
        g_ao[ro1 + pp0 + 2] = uaf(f2tf(o[u][3] * inv1));
    }
}

// ---------------------------------------------------------------------------
// Kernel 3: output projection + bias
// ---------------------------------------------------------------------------
__global__ __launch_bounds__(256, 2) void out_gemm(
    const float* __restrict__ bias, float* __restrict__ out)
{
    extern __shared__ float sm[];
    float c[16][4];
#pragma unroll
    for (int i = 0; i < 16; i++)
#pragma unroll
        for (int j = 0; j < 4; j++) c[i][j] = 0.f;

    gemm_core(g_ao, g_wo, blockIdx.y * 128, blockIdx.x * 128, c, sm);

    const int lane = threadIdx.x & 31, warp = threadIdx.x >> 5;
    const int g = lane >> 2, t = lane & 3;
    const int wm = warp >> 2, wn = warp & 3;

#pragma unroll
    for (int mt = 0; mt < 4; mt++) {
#pragma unroll
        for (int nt = 0; nt < 4; nt++) {
            int rowb = blockIdx.y * 128 + wm * 64 + mt * 16 + g;
            int col  = blockIdx.x * 128 + wn * 32 + nt * 8 + 2 * t;
            float2 bv = *(const float2*)&bias[col];
#pragma unroll
            for (int half = 0; half < 2; half++) {
                int row = rowb + half * 8;
                float2 v = make_float2(c[mt * 4 + nt][half * 2] + bv.x,
                                       c[mt * 4 + nt][half * 2 + 1] + bv.y);
                *(float2*)&out[(size_t)row * CHN + col] = v;
            }
        }
    }
}

// ---------------------------------------------------------------------------
extern "C" void kernel_launch(void* const* d_in, const int* in_sizes, int n_in,
                              void* d_out, int out_size)
{
    const float* X    = (const float*)d_in[0];
    const float* Wq   = (const float*)d_in[1];
    const float* Wk   = (const float*)d_in[2];
    const float* Wv   = (const float*)d_in[3];
    const float* Wout = (const float*)d_in[4];
    const float* bout = (const float*)d_in[5];
    float* out = (float*)d_out;

    const int NX = MTOT * CHN / 4, NW = CHN * CHN / 4;
    cvt_all<<<(NX + 4 * NW + 255) / 256, 256>>>(X, Wq, Wk, Wv, Wout);

    cudaFuncSetAttribute(qkv_gemm,
                         cudaFuncAttributeMaxDynamicSharedMemorySize, GEMM_SMEM);
    qkv_gemm<<<dim3(CHN / 128, MTOT / 128, 3), 256, GEMM_SMEM>>>();

    cudaFuncSetAttribute(attn_kernel,
                         cudaFuncAttributeMaxDynamicSharedMemorySize, ATTN_SMEM);
    attn_kernel<<<dim3(SEQ / 64, BHN), 256, ATTN_SMEM>>>();

    cudaFuncSetAttribute(out_gemm,
                         cudaFuncAttributeMaxDynamicSharedMemorySize, GEMM_SMEM);
    out_gemm<<<dim3(CHN / 128, MTOT / 128), 256, GEMM_SMEM>>>(bout, out);
}